// round 4
// baseline (speedup 1.0000x reference)
#include <cuda_runtime.h>

#define N_NODES  100000
#define N_EDGES  1600000
#define N_GRAPHS 512
#define F        32

#define SCAN_B   1024
#define NB       ((N_NODES + SCAN_B - 1) / SCAN_B)   // 98 scan blocks

// ---------------- scratch (static __device__ globals) ----------------------
__device__ __align__(128) int   g_hist[N_NODES];        // in-degree (no self loop)
__device__ __align__(128) int   g_off[N_NODES + 1];     // CSR offsets
__device__ __align__(128) int   g_pos[N_NODES];         // scatter cursors
__device__ __align__(128) int   g_blocksum[NB];
__device__ __align__(128) int2  g_csr[N_EDGES];         // (src, norm-as-bits)
__device__ __align__(128) float g_dinv[N_NODES];
__device__ __align__(128) float g_bufA[N_NODES * F];    // xw1
__device__ __align__(128) float g_bufB[N_NODES * F];    // xw2
__device__ __align__(128) float g_sums[N_GRAPHS * F];
__device__ __align__(128) float g_cnt[N_GRAPHS];

// ---------------- K0: zero hist + pool accumulators ------------------------
__global__ void k_init() {
    int i = blockIdx.x * blockDim.x + threadIdx.x;
    if (i < N_NODES) g_hist[i] = 0;
    if (i < N_GRAPHS * F) g_sums[i] = 0.0f;
    if (i < N_GRAPHS) g_cnt[i] = 0.0f;
}

// ---------------- K1: in-degree histogram ----------------------------------
__global__ void k_hist(const int* __restrict__ ei) {
    int e = blockIdx.x * blockDim.x + threadIdx.x;
    if (e >= N_EDGES) return;
    atomicAdd(&g_hist[ei[N_EDGES + e]], 1);
}

// ---------------- K2: per-block exclusive scan of hist ---------------------
__global__ void k_scan1() {
    __shared__ int sh[SCAN_B];
    int tid = threadIdx.x;
    int i = blockIdx.x * SCAN_B + tid;
    int v = (i < N_NODES) ? g_hist[i] : 0;
    sh[tid] = v;
    __syncthreads();
#pragma unroll
    for (int off = 1; off < SCAN_B; off <<= 1) {
        int t = (tid >= off) ? sh[tid - off] : 0;
        __syncthreads();
        sh[tid] += t;
        __syncthreads();
    }
    if (i < N_NODES) g_off[i] = sh[tid] - v;       // exclusive (local)
    if (tid == SCAN_B - 1) g_blocksum[blockIdx.x] = sh[tid];
}

// ---------------- K3: add blocksum prefix (scan2 fused in) -----------------
__global__ void k_scan3() {
    __shared__ int s_pre;
    int tid = threadIdx.x;
    if (tid == 0) s_pre = 0;
    __syncthreads();
    if (tid < (int)blockIdx.x) atomicAdd(&s_pre, g_blocksum[tid]);
    __syncthreads();
    int pre = s_pre;
    int i = blockIdx.x * SCAN_B + tid;
    if (i < N_NODES) {
        int o = g_off[i] + pre;
        g_off[i] = o;
        g_pos[i] = o;
    }
    if (i == 0) g_off[N_NODES] = N_EDGES;
}

// ---------------- K4: dinv = rsqrt(deg+1); xw1 = x@W1 ----------------------
__global__ void k_l1_init(const float* __restrict__ x,
                          const float* __restrict__ W1) {
    int idx = blockIdx.x * blockDim.x + threadIdx.x;
    if (idx >= N_NODES * F) return;
    int n = idx >> 5, f = idx & 31;
    float di = rsqrtf((float)g_hist[n] + 1.0f);
    if (f == 0) g_dinv[n] = di;
    float x0 = x[n * 3 + 0], x1 = x[n * 3 + 1], x2 = x[n * 3 + 2];
    g_bufA[idx] = x0 * W1[f] + x1 * W1[F + f] + x2 * W1[2 * F + f];
}

// ---------------- K5: scatter (src, norm) into CSR -------------------------
__global__ void k_scatter(const int* __restrict__ ei) {
    int e = blockIdx.x * blockDim.x + threadIdx.x;
    if (e >= N_EDGES) return;
    int s = ei[e];
    int d = ei[N_EDGES + e];
    int p = atomicAdd(&g_pos[d], 1);
    float nm = g_dinv[s] * g_dinv[d];
    g_csr[p] = make_int2(s, __float_as_int(nm));
}

// ---------------- gather-reduce core: 8-wide MLP, broadcast rec loads ------
__device__ __forceinline__ float agg_node(const float* __restrict__ feat,
                                          int beg, int end, int lane,
                                          float acc) {
    for (int j = beg; j < end; j += 8) {
        int   sidx[8];
        float nm[8];
#pragma unroll
        for (int u = 0; u < 8; u++) {
            int idx = j + u;
            bool ok = (idx < end);
            int2 rec = g_csr[ok ? idx : beg];   // uniform addr -> 1 wavefront
            sidx[u] = rec.x;
            nm[u] = ok ? __int_as_float(rec.y) : 0.0f;
        }
        float v[8];
#pragma unroll
        for (int u = 0; u < 8; u++) v[u] = feat[sidx[u] * F + lane];
#pragma unroll
        for (int u = 0; u < 8; u++) acc = fmaf(v[u], nm[u], acc);
    }
    return acc;
}

// ---------------- K6: agg layer1 + relu(b1) + @W2 fused --------------------
__global__ void k_agg1(const float* __restrict__ b1,
                       const float* __restrict__ W2) {
    __shared__ float W2s[F * F];
    int tid = threadIdx.x;
    for (int i = tid; i < F * F; i += blockDim.x) W2s[i] = W2[i];
    __syncthreads();
    int w = (blockIdx.x * blockDim.x + tid) >> 5;
    int lane = tid & 31;
    if (w >= N_NODES) return;
    int beg = g_off[w], end = g_off[w + 1];
    float di = g_dinv[w];
    float acc = g_bufA[w * F + lane] * di * di;        // self loop
    acc = agg_node(g_bufA, beg, end, lane, acc);
    // epilogue: h1 = relu(acc + b1); xw2 = h1 @ W2
    float h = fmaxf(acc + b1[lane], 0.0f);
    float o = 0.0f;
#pragma unroll
    for (int k = 0; k < F; k++) {
        float hk = __shfl_sync(0xffffffffu, h, k);
        o = fmaf(hk, W2s[k * F + lane], o);
    }
    g_bufB[w * F + lane] = o;
}

// ---------------- K7: agg layer2 + relu(b2) + pool fused -------------------
__global__ void k_agg2(const float* __restrict__ b2,
                       const int* __restrict__ batch) {
    int tid = threadIdx.x;
    int w = (blockIdx.x * blockDim.x + tid) >> 5;
    int lane = tid & 31;
    if (w >= N_NODES) return;
    int beg = g_off[w], end = g_off[w + 1];
    float di = g_dinv[w];
    float acc = g_bufB[w * F + lane] * di * di;        // self loop
    acc = agg_node(g_bufB, beg, end, lane, acc);
    float h = fmaxf(acc + b2[lane], 0.0f);
    int g = batch[w];
    atomicAdd(&g_sums[g * F + lane], h);
    if (lane == 0) atomicAdd(&g_cnt[g], 1.0f);
}

// ---------------- K8: out = (sums/cnt)@Wl + bl -----------------------------
__global__ void k_out(const float* __restrict__ Wl,
                      const float* __restrict__ bl,
                      float* __restrict__ out) {
    int idx = blockIdx.x * blockDim.x + threadIdx.x;
    if (idx >= N_GRAPHS * 2) return;
    int g = idx >> 1, j = idx & 1;
    float inv = 1.0f / fmaxf(g_cnt[g], 1.0f);
    float acc = 0.0f;
#pragma unroll
    for (int f = 0; f < F; f++) acc += g_sums[g * F + f] * Wl[f * 2 + j];
    out[idx] = acc * inv + bl[j];
}

// ---------------- launch ---------------------------------------------------
extern "C" void kernel_launch(void* const* d_in, const int* in_sizes, int n_in,
                              void* d_out, int out_size) {
    const float* x     = (const float*)d_in[0];
    const int*   ei    = (const int*)d_in[1];    // int64 -> int32 by harness
    const int*   batch = (const int*)d_in[2];
    const float* W1    = (const float*)d_in[3];
    const float* b1    = (const float*)d_in[4];
    const float* W2    = (const float*)d_in[5];
    const float* b2    = (const float*)d_in[6];
    const float* Wl    = (const float*)d_in[7];
    const float* bl    = (const float*)d_in[8];
    float*       out   = (float*)d_out;

    const int TB = 256;
    k_init   <<<(N_NODES + TB - 1) / TB, TB>>>();
    k_hist   <<<(N_EDGES + TB - 1) / TB, TB>>>(ei);
    k_scan1  <<<NB, SCAN_B>>>();
    k_scan3  <<<NB, SCAN_B>>>();
    k_l1_init<<<(N_NODES * F + TB - 1) / TB, TB>>>(x, W1);
    k_scatter<<<(N_EDGES + TB - 1) / TB, TB>>>(ei);
    k_agg1   <<<(N_NODES * 32 + TB - 1) / TB, TB>>>(b1, W2);
    k_agg2   <<<(N_NODES * 32 + TB - 1) / TB, TB>>>(b2, batch);
    k_out    <<<(N_GRAPHS * 2 + TB - 1) / TB, TB>>>(Wl, bl, out);
}

// round 7
// speedup vs baseline: 1.0123x; 1.0123x over previous
#include <cuda_runtime.h>

#define N_NODES  100000
#define N_EDGES  1600000
#define N_GRAPHS 512
#define F        32
#define SCAN_B   1024
#define NB       ((N_NODES + SCAN_B - 1) / SCAN_B)   // 98 blocks

// ---------------- scratch (static __device__ globals; zero at load) --------
__device__ __align__(128) int   g_hist[N_NODES];      // zeroed by k_agg2 for next run
__device__ __align__(128) int   g_off[N_NODES + 1];   // CSR offsets
__device__ __align__(128) int   g_pos[N_NODES];       // scatter cursors
__device__ __align__(128) int   g_blocksum[NB];
__device__ __align__(128) int2  g_csr[N_EDGES];       // (src, norm-as-bits)
__device__ __align__(128) float g_dinv[N_NODES];
__device__ __align__(128) float g_bufA[N_NODES * F];  // xw1
__device__ __align__(128) float g_bufB[N_NODES * F];  // xw2
__device__ __align__(128) float g_sums[N_GRAPHS * F];
__device__ __align__(128) float g_cnt[N_GRAPHS];

// ---------------- K1: in-degree histogram ----------------------------------
__global__ void k_hist(const int* __restrict__ ei) {
    int e = blockIdx.x * blockDim.x + threadIdx.x;
    if (e >= N_EDGES) return;
    atomicAdd(&g_hist[ei[N_EDGES + e]], 1);
}

// ---------------- K2: per-block scan + dinv + zero pool accumulators -------
__global__ void __launch_bounds__(SCAN_B) k_scan1() {
    __shared__ int sh[SCAN_B];
    int tid = threadIdx.x;
    int i = blockIdx.x * SCAN_B + tid;
    int v = (i < N_NODES) ? g_hist[i] : 0;
    sh[tid] = v;
    __syncthreads();
#pragma unroll
    for (int off = 1; off < SCAN_B; off <<= 1) {
        int t = (tid >= off) ? sh[tid - off] : 0;
        __syncthreads();
        sh[tid] += t;
        __syncthreads();
    }
    if (i < N_NODES) {
        g_off[i] = sh[tid] - v;                   // exclusive (block-local)
        g_dinv[i] = rsqrtf((float)v + 1.0f);      // deg includes self-loop
    }
    if (tid == SCAN_B - 1) g_blocksum[blockIdx.x] = sh[tid];
    // zero pool accumulators for THIS run (consumed by k_agg2/k_out later)
    if (i < N_GRAPHS * F) g_sums[i] = 0.0f;
    if (i < N_GRAPHS) g_cnt[i] = 0.0f;
}

// ---------------- K3: scan finalize (atomic prefix) + xw1 = x@W1 -----------
__global__ void __launch_bounds__(SCAN_B)
k_scan3_l1(const float* __restrict__ x, const float* __restrict__ W1) {
    __shared__ int   s_pre;
    __shared__ float s_W1[96];
    int tid = threadIdx.x, b = blockIdx.x;
    if (tid == 0) s_pre = 0;
    if (tid < 96) s_W1[tid] = W1[tid];
    __syncthreads();
    if (tid < b) atomicAdd(&s_pre, g_blocksum[tid]);   // NB=98 <= blockDim
    __syncthreads();
    int pre = s_pre;
    int i = b * SCAN_B + tid;
    if (i < N_NODES) {
        int o = g_off[i] + pre;
        g_off[i] = o;
        g_pos[i] = o;
    }
    if (i == 0) g_off[N_NODES] = N_EDGES;

    // ---- phase 2: xw1 = x @ W1 (warp per node, grid-stride) ----
    int lane = tid & 31, wid = tid >> 5;
    float w0 = s_W1[lane], w1 = s_W1[32 + lane], w2 = s_W1[64 + lane];
    for (int n = b * 32 + wid; n < N_NODES; n += NB * 32) {
        float x0 = x[n * 3 + 0];   // warp-uniform broadcast loads
        float x1 = x[n * 3 + 1];
        float x2 = x[n * 3 + 2];
        g_bufA[n * F + lane] = x0 * w0 + x1 * w1 + x2 * w2;  // coalesced 128B
    }
}

// ---------------- K4: scatter (src, norm) into CSR -------------------------
__global__ void k_scatter(const int* __restrict__ ei) {
    int e = blockIdx.x * blockDim.x + threadIdx.x;
    if (e >= N_EDGES) return;
    int s = ei[e];
    int d = ei[N_EDGES + e];
    int p = atomicAdd(&g_pos[d], 1);
    float nm = g_dinv[s] * g_dinv[d];
    g_csr[p] = make_int2(s, __float_as_int(nm));
}

// ---------------- gather-reduce core: 8-wide MLP ---------------------------
__device__ __forceinline__ float agg_node(const float* __restrict__ feat,
                                          int beg, int end, int lane,
                                          float acc) {
    for (int j = beg; j < end; j += 8) {
        int   sidx[8];
        float nm[8];
#pragma unroll
        for (int u = 0; u < 8; u++) {
            int idx = j + u;
            bool ok = (idx < end);
            int2 rec = g_csr[ok ? idx : beg];
            sidx[u] = rec.x;
            nm[u] = ok ? __int_as_float(rec.y) : 0.0f;
        }
        float v[8];
#pragma unroll
        for (int u = 0; u < 8; u++) v[u] = feat[sidx[u] * F + lane];
#pragma unroll
        for (int u = 0; u < 8; u++) acc = fmaf(v[u], nm[u], acc);
    }
    return acc;
}

// ---------------- K5: agg layer1 + relu(b1) + @W2 fused --------------------
__global__ void k_agg1(const float* __restrict__ b1,
                       const float* __restrict__ W2) {
    __shared__ float W2s[F * F];
    int tid = threadIdx.x;
    for (int i = tid; i < F * F; i += blockDim.x) W2s[i] = W2[i];
    __syncthreads();
    int w = (blockIdx.x * blockDim.x + tid) >> 5;
    int lane = tid & 31;
    if (w >= N_NODES) return;
    int beg = g_off[w], end = g_off[w + 1];
    float di = g_dinv[w];
    float acc = g_bufA[w * F + lane] * di * di;        // self loop
    acc = agg_node(g_bufA, beg, end, lane, acc);
    float h = fmaxf(acc + b1[lane], 0.0f);
    float o = 0.0f;
#pragma unroll
    for (int k = 0; k < F; k++) {
        float hk = __shfl_sync(0xffffffffu, h, k);
        o = fmaf(hk, W2s[k * F + lane], o);
    }
    g_bufB[w * F + lane] = o;
}

// ---------------- K6: agg layer2 + relu(b2) + pool (+ hist re-zero) --------
__global__ void k_agg2(const float* __restrict__ b2,
                       const int* __restrict__ batch) {
    int tid = threadIdx.x;
    int gidx = blockIdx.x * blockDim.x + tid;
    // re-zero g_hist for the NEXT run (plain stores; kernel-boundary ordered;
    // g_hist is not used by this kernel)
    if (gidx < N_NODES) g_hist[gidx] = 0;

    int w = gidx >> 5;
    int lane = tid & 31;
    if (w >= N_NODES) return;
    int beg = g_off[w], end = g_off[w + 1];
    float di = g_dinv[w];
    float acc = g_bufB[w * F + lane] * di * di;        // self loop
    acc = agg_node(g_bufB, beg, end, lane, acc);
    float h = fmaxf(acc + b2[lane], 0.0f);
    int g = batch[w];
    atomicAdd(&g_sums[g * F + lane], h);
    if (lane == 0) atomicAdd(&g_cnt[g], 1.0f);
}

// ---------------- K7: out = (sums/cnt)@Wl + bl -----------------------------
__global__ void k_out(const float* __restrict__ Wl,
                      const float* __restrict__ bl,
                      float* __restrict__ out) {
    int idx = blockIdx.x * blockDim.x + threadIdx.x;
    if (idx >= N_GRAPHS * 2) return;
    int g = idx >> 1, j = idx & 1;
    float inv = 1.0f / fmaxf(g_cnt[g], 1.0f);
    float acc = 0.0f;
#pragma unroll
    for (int f = 0; f < F; f++) acc += g_sums[g * F + f] * Wl[f * 2 + j];
    out[idx] = acc * inv + bl[j];
}

// ---------------- launch: 7 kernels ----------------------------------------
extern "C" void kernel_launch(void* const* d_in, const int* in_sizes, int n_in,
                              void* d_out, int out_size) {
    const float* x     = (const float*)d_in[0];
    const int*   ei    = (const int*)d_in[1];    // int64 -> int32 by harness
    const int*   batch = (const int*)d_in[2];
    const float* W1    = (const float*)d_in[3];
    const float* b1    = (const float*)d_in[4];
    const float* W2    = (const float*)d_in[5];
    const float* b2    = (const float*)d_in[6];
    const float* Wl    = (const float*)d_in[7];
    const float* bl    = (const float*)d_in[8];
    float*       out   = (float*)d_out;

    const int TB = 256;
    k_hist    <<<(N_EDGES + TB - 1) / TB, TB>>>(ei);
    k_scan1   <<<NB, SCAN_B>>>();
    k_scan3_l1<<<NB, SCAN_B>>>(x, W1);
    k_scatter <<<(N_EDGES + TB - 1) / TB, TB>>>(ei);
    k_agg1    <<<(N_NODES * 32 + TB - 1) / TB, TB>>>(b1, W2);
    k_agg2    <<<(N_NODES * 32 + TB - 1) / TB, TB>>>(b2, batch);
    k_out     <<<(N_GRAPHS * 2 + TB - 1) / TB, TB>>>(Wl, bl, out);
}